// round 5
// baseline (speedup 1.0000x reference)
#include <cuda_runtime.h>
#include <cstdint>

// Problem constants (fixed by the reference)
#define BB 2
#define LL 1024
#define MM 8
#define NN 16
#define CC 16
#define HH 64
#define WW 64
#define VOTES (MM * NN)            // 128
#define SLAB  (CC * HH * WW)       // 65536 floats = 256 KB per (b,l)
#define CGRP  4                    // channels per quantum
#define NGRP  (CC / CGRP)          // 4 quanta per slab
#define PLANE (HH * WW)            // 4096
#define QFLOATS (CGRP * PLANE)     // 16384 floats = 64 KB per quantum
#define NQ    (BB * LL * NGRP)     // 8192 quanta
#define NCTA  (152 * 8)            // persistent grid: one wave on GB300

// Persistent-CTA version of the R2 kernel: 1216 resident CTAs each loop over
// ~6.7 quanta. Eliminates the 6 wave transitions (~2360 cyc each) and the
// per-CTA prologue restarts that left the store stream idle between waves.
// Inner body is identical to R2: gather -> 64 KB zero stream -> 512 atomics.
__global__ __launch_bounds__(256, 8)
void ht_vote_kernel(const float* __restrict__ feats,   // [B,L,N,C]
                    const int*   __restrict__ vsrc,    // [B,L,2]
                    const int*   __restrict__ vdst,    // [B,L,2]
                    const int*   __restrict__ isrc,    // [B,L,M]
                    const int*   __restrict__ idst,    // [B,L,N]
                    float* __restrict__ out)           // [B,L,C,H,W]
{
    __shared__ int    sbin[VOTES];
    __shared__ float4 sw[VOTES];       // this quantum's 4 channels per vote

    const int t = threadIdx.x;

    for (int q = blockIdx.x; q < NQ; q += NCTA) {
        const int bl = q >> 2;         // NGRP == 4
        const int g  = q & 3;          // channel group
        const int b  = bl >> 10;       // LL == 1024

        // ---- Gather chain: loads issued here, results consumed only after
        // the store loop -> scoreboard lets the ~3 dependent L2 latencies
        // hide under the 64 KB store stream.
        int    bin = -1;
        float4 w   = make_float4(0.f, 0.f, 0.f, 0.f);
        if (t < VOTES) {
            const int m = t >> 4;      // NN == 16
            const int n = t & 15;

            const int s  = isrc[bl * MM + m];
            const int d  = idst[(b * LL + s) * NN + n];
            const int sy = vsrc[(b * LL + s) * 2 + 0];
            const int sx = vsrc[(b * LL + s) * 2 + 1];
            const int dy = vdst[(b * LL + d) * 2 + 0];
            const int dx = vdst[(b * LL + d) * 2 + 1];

            // voxels are int32: floor(float sub) == integer sub exactly
            const int by = dy - sy + HH / 2;
            const int bx = dx - sx + WW / 2;
            if (((unsigned)by < HH) & ((unsigned)bx < WW)) bin = by * WW + bx;

            // 4 channels of this vote's weights (16B, coalesced, L2-hot)
            w = ((const float4*)(feats + (((size_t)(b * LL + s)) * NN + n) * CC))[g];
        }

        float* base = out + (size_t)bl * SLAB + g * QFLOATS;

        // ---- Stream-zero this quantum's 64 KB (16 float4 per thread) ----
        {
            float4* b4 = (float4*)base;
            const float4 z = make_float4(0.f, 0.f, 0.f, 0.f);
#pragma unroll
            for (int i = 0; i < QFLOATS / 4 / 256; i++)
                b4[t + i * 256] = z;
        }

        // ---- Publish votes to smem ----
        if (t < VOTES) {
            sbin[t] = bin;
            sw[t]   = w;
        }
        __syncthreads();   // zero-stores & smem votes before atomics

        // ---- Scatter: 128 votes x 4 channels = 512 atomicAdds ----
#pragma unroll
        for (int k = 0; k < 2; k++) {
            const int i  = t + k * 256;   // 0..511
            const int v  = i >> 2;        // vote
            const int c  = i & 3;         // channel within group
            const int bn = sbin[v];
            if (bn >= 0)
                atomicAdd(base + c * PLANE + bn, ((const float*)&sw[v])[c]);
        }
        __syncthreads();   // atomics read sbin/sw before next iter overwrites
    }
}

extern "C" void kernel_launch(void* const* d_in, const int* in_sizes, int n_in,
                              void* d_out, int out_size)
{
    const float* feats = (const float*)d_in[0];   // [B,L,N,C] f32
    const int*   vsrc  = (const int*)  d_in[1];   // [B,L,2]   i32
    const int*   vdst  = (const int*)  d_in[2];   // [B,L,2]   i32
    const int*   isrc  = (const int*)  d_in[3];   // [B,L,M]   i32
    const int*   idst  = (const int*)  d_in[4];   // [B,L,N]   i32
    float*       out   = (float*)d_out;           // [B,L,C,H,W] f32

    ht_vote_kernel<<<NCTA, 256>>>(feats, vsrc, vdst, isrc, idst, out);
}

// round 6
// speedup vs baseline: 1.2103x; 1.2103x over previous
#include <cuda_runtime.h>
#include <cstdint>

// Problem constants (fixed by the reference)
#define BB 2
#define LL 1024
#define MM 8
#define NN 16
#define CC 16
#define HH 64
#define WW 64
#define VOTES (MM * NN)            // 128
#define SLAB  (CC * HH * WW)       // 65536 floats = 256 KB per (b,l)
#define CGRP  4                    // channels per quantum
#define NGRP  (CC / CGRP)          // 4 quanta per slab
#define PLANE (HH * WW)            // 4096
#define QFLOATS (CGRP * PLANE)     // 16384 floats = 64 KB per quantum

// R2 structure (champion) with 256-bit zero stores (STG.256, sm_100+).
// One CTA = one quantum = (slab bl, channel-group g): gather votes ->
// stream-zero 64 KB with st.global.v8.f32 -> 512 global atomicAdds (REDG,
// L2-hot lines). No .cs anywhere (evict-first measurably hurt DRAM eff).
__global__ __launch_bounds__(256, 8)
void ht_vote_kernel(const float* __restrict__ feats,   // [B,L,N,C]
                    const int*   __restrict__ vsrc,    // [B,L,2]
                    const int*   __restrict__ vdst,    // [B,L,2]
                    const int*   __restrict__ isrc,    // [B,L,M]
                    const int*   __restrict__ idst,    // [B,L,N]
                    float* __restrict__ out)           // [B,L,C,H,W]
{
    __shared__ int    sbin[VOTES];
    __shared__ float4 sw[VOTES];       // this quantum's 4 channels per vote

    const int q  = blockIdx.x;         // 0 .. B*L*NGRP-1
    const int bl = q >> 2;             // NGRP == 4
    const int g  = q & 3;              // channel group
    const int b  = bl >> 10;           // LL == 1024
    const int t  = threadIdx.x;

    // ---- Gather chain: issued before the store stream; the ~3 dependent
    // L2 latencies hide under the 64 KB of independent stores.
    int    bin = -1;
    float4 w   = make_float4(0.f, 0.f, 0.f, 0.f);
    if (t < VOTES) {
        const int m = t >> 4;          // NN == 16
        const int n = t & 15;

        const int s  = isrc[bl * MM + m];
        const int d  = idst[(b * LL + s) * NN + n];
        const int sy = vsrc[(b * LL + s) * 2 + 0];
        const int sx = vsrc[(b * LL + s) * 2 + 1];
        const int dy = vdst[(b * LL + d) * 2 + 0];
        const int dx = vdst[(b * LL + d) * 2 + 1];

        // voxels are int32: floor(float sub) == integer sub exactly
        const int by = dy - sy + HH / 2;
        const int bx = dx - sx + WW / 2;
        if (((unsigned)by < HH) & ((unsigned)bx < WW)) bin = by * WW + bx;

        // 4 channels of this vote's weights (16B, coalesced, L2-hot)
        w = ((const float4*)(feats + (((size_t)(b * LL + s)) * NN + n) * CC))[g];
    }

    float* base = out + (size_t)bl * SLAB + g * QFLOATS;

    // ---- Stream-zero this quantum's 64 KB with STG.256 ----
    // 2048 x 32B chunks / 256 threads = 8 per thread, all independent,
    // fully coalesced (warp-instruction = 1 KB contiguous burst).
    {
        const float z = 0.f;
#pragma unroll
        for (int i = 0; i < QFLOATS / 8 / 256; i++) {
            float* p = base + 8 * (t + i * 256);
            asm volatile(
                "st.global.v8.f32 [%0], {%1,%2,%3,%4,%5,%6,%7,%8};"
                :: "l"(p), "f"(z), "f"(z), "f"(z), "f"(z),
                           "f"(z), "f"(z), "f"(z), "f"(z)
                : "memory");
        }
    }

    // ---- Publish votes to smem ----
    if (t < VOTES) {
        sbin[t] = bin;
        sw[t]   = w;
    }
    __syncthreads();   // orders zero-stores & smem votes before atomics
                       // (quantum region is CTA-private)

    // ---- Scatter: 128 votes x 4 channels = 512 atomicAdds (2/thread) ----
#pragma unroll
    for (int k = 0; k < 2; k++) {
        const int i  = t + k * 256;    // 0..511
        const int v  = i >> 2;         // vote
        const int c  = i & 3;          // channel within group
        const int bn = sbin[v];
        if (bn >= 0)
            atomicAdd(base + c * PLANE + bn, ((const float*)&sw[v])[c]);
    }
}

extern "C" void kernel_launch(void* const* d_in, const int* in_sizes, int n_in,
                              void* d_out, int out_size)
{
    const float* feats = (const float*)d_in[0];   // [B,L,N,C] f32
    const int*   vsrc  = (const int*)  d_in[1];   // [B,L,2]   i32
    const int*   vdst  = (const int*)  d_in[2];   // [B,L,2]   i32
    const int*   isrc  = (const int*)  d_in[3];   // [B,L,M]   i32
    const int*   idst  = (const int*)  d_in[4];   // [B,L,N]   i32
    float*       out   = (float*)d_out;           // [B,L,C,H,W] f32

    ht_vote_kernel<<<BB * LL * NGRP, 256>>>(feats, vsrc, vdst, isrc, idst, out);
}

// round 9
// speedup vs baseline: 1.2868x; 1.0632x over previous
#include <cuda_runtime.h>
#include <cstdint>

// Problem constants (fixed by the reference)
#define BB 2
#define LL 1024
#define MM 8
#define NN 16
#define CC 16
#define HH 64
#define WW 64
#define VOTES (MM * NN)            // 128
#define SLAB  (CC * HH * WW)       // 65536 floats = 256 KB per (b,l)
#define CGRP  2                    // channels per quantum  (R2 had 4)
#define NGRP  (CC / CGRP)          // 8 quanta per slab
#define PLANE (HH * WW)            // 4096
#define QFLOATS (CGRP * PLANE)     // 8192 floats = 32 KB per quantum

// Champion R2 structure, quantum-size sweep CGRP 4 -> 2.
// One CTA = one quantum = (slab bl, channel-group g): gather votes ->
// stream-zero 32 KB with plain STG.128 (measured best vs .cs / STG.256) ->
// 256 global atomicAdds onto just-written (L2-hot) lines.
// 16384 quanta / ~1184 slots: quantization loss ~0.6%, and the per-CTA
// atomic tail halves, hiding better under neighboring CTAs' store streams.
__global__ __launch_bounds__(256, 8)
void ht_vote_kernel(const float* __restrict__ feats,   // [B,L,N,C]
                    const int*   __restrict__ vsrc,    // [B,L,2]
                    const int*   __restrict__ vdst,    // [B,L,2]
                    const int*   __restrict__ isrc,    // [B,L,M]
                    const int*   __restrict__ idst,    // [B,L,N]
                    float* __restrict__ out)           // [B,L,C,H,W]
{
    __shared__ int    sbin[VOTES];
    __shared__ float2 sw[VOTES];       // this quantum's 2 channels per vote

    const int q  = blockIdx.x;         // 0 .. B*L*NGRP-1
    const int bl = q >> 3;             // NGRP == 8
    const int g  = q & 7;              // channel group
    const int b  = bl >> 10;           // LL == 1024
    const int t  = threadIdx.x;

    // ---- Gather chain: issued before the store stream; the ~3 dependent
    // L2 latencies hide under the 32 KB of independent stores.
    int    bin = -1;
    float2 w   = make_float2(0.f, 0.f);
    if (t < VOTES) {
        const int m = t >> 4;          // NN == 16
        const int n = t & 15;

        const int s  = isrc[bl * MM + m];
        const int d  = idst[(b * LL + s) * NN + n];
        const int sy = vsrc[(b * LL + s) * 2 + 0];
        const int sx = vsrc[(b * LL + s) * 2 + 1];
        const int dy = vdst[(b * LL + d) * 2 + 0];
        const int dx = vdst[(b * LL + d) * 2 + 1];

        // voxels are int32: floor(float sub) == integer sub exactly
        const int by = dy - sy + HH / 2;
        const int bx = dx - sx + WW / 2;
        if (((unsigned)by < HH) & ((unsigned)bx < WW)) bin = by * WW + bx;

        // 2 channels of this vote's weights (8B, coalesced, L2-hot)
        w = ((const float2*)(feats + (((size_t)(b * LL + s)) * NN + n) * CC))[g];
    }

    float* base = out + (size_t)bl * SLAB + g * QFLOATS;

    // ---- Stream-zero this quantum's 32 KB (8 float4 per thread) ----
    {
        float4* b4 = (float4*)base;
        const float4 z = make_float4(0.f, 0.f, 0.f, 0.f);
#pragma unroll
        for (int i = 0; i < QFLOATS / 4 / 256; i++)
            b4[t + i * 256] = z;
    }

    // ---- Publish votes to smem ----
    if (t < VOTES) {
        sbin[t] = bin;
        sw[t]   = w;
    }
    __syncthreads();   // orders zero-stores & smem votes before atomics
                       // (quantum region is CTA-private)

    // ---- Scatter: 128 votes x 2 channels = 256 atomicAdds (1/thread) ----
    {
        const int v  = t >> 1;         // vote
        const int c  = t & 1;          // channel within group
        const int bn = sbin[v];
        if (bn >= 0)
            atomicAdd(base + c * PLANE + bn, ((const float*)&sw[v])[c]);
    }
}

extern "C" void kernel_launch(void* const* d_in, const int* in_sizes, int n_in,
                              void* d_out, int out_size)
{
    const float* feats = (const float*)d_in[0];   // [B,L,N,C] f32
    const int*   vsrc  = (const int*)  d_in[1];   // [B,L,2]   i32
    const int*   vdst  = (const int*)  d_in[2];   // [B,L,2]   i32
    const int*   isrc  = (const int*)  d_in[3];   // [B,L,M]   i32
    const int*   idst  = (const int*)  d_in[4];   // [B,L,N]   i32
    float*       out   = (float*)d_out;           // [B,L,C,H,W] f32

    ht_vote_kernel<<<BB * LL * NGRP, 256>>>(feats, vsrc, vdst, isrc, idst, out);
}

// round 10
// speedup vs baseline: 1.3316x; 1.0348x over previous
#include <cuda_runtime.h>
#include <cstdint>

// Problem constants (fixed by the reference)
#define BB 2
#define LL 1024
#define MM 8
#define NN 16
#define CC 16
#define HH 64
#define WW 64
#define VOTES (MM * NN)            // 128
#define SLAB  (CC * HH * WW)       // 65536 floats = 256 KB per (b,l)
#define CGRP  2                    // channels per quantum
#define NGRP  (CC / CGRP)          // 8 quanta per slab
#define PLANE (HH * WW)            // 4096
#define QFLOATS (CGRP * PLANE)     // 8192 floats = 32 KB per quantum

// Converged structure (R9 champion) minus the smem vote round-trip:
// one CTA = one quantum = (slab bl, channel-group g). Gather votes into
// registers -> stream-zero 32 KB with plain STG.128 (measured best vs .cs /
// STG.256 / smem-staged / persistent variants) -> __syncthreads (orders the
// cooperative zero against the scattered atomics; also CUDA block-level
// visibility fence for the global stores) -> each vote thread issues its own
// 2 atomicAdds straight from registers. Threads 128-255 retire at the barrier.
__global__ __launch_bounds__(256, 8)
void ht_vote_kernel(const float* __restrict__ feats,   // [B,L,N,C]
                    const int*   __restrict__ vsrc,    // [B,L,2]
                    const int*   __restrict__ vdst,    // [B,L,2]
                    const int*   __restrict__ isrc,    // [B,L,M]
                    const int*   __restrict__ idst,    // [B,L,N]
                    float* __restrict__ out)           // [B,L,C,H,W]
{
    const int q  = blockIdx.x;         // 0 .. B*L*NGRP-1
    const int bl = q >> 3;             // NGRP == 8
    const int g  = q & 7;              // channel group
    const int b  = bl >> 10;           // LL == 1024
    const int t  = threadIdx.x;

    // ---- Gather chain: issued before the store stream; the ~3 dependent
    // L2 latencies hide under the 32 KB of independent stores.
    int    bin = -1;
    float2 w   = make_float2(0.f, 0.f);
    if (t < VOTES) {
        const int m = t >> 4;          // NN == 16
        const int n = t & 15;

        const int s  = isrc[bl * MM + m];
        const int d  = idst[(b * LL + s) * NN + n];
        const int sy = vsrc[(b * LL + s) * 2 + 0];
        const int sx = vsrc[(b * LL + s) * 2 + 1];
        const int dy = vdst[(b * LL + d) * 2 + 0];
        const int dx = vdst[(b * LL + d) * 2 + 1];

        // voxels are int32: floor(float sub) == integer sub exactly
        const int by = dy - sy + HH / 2;
        const int bx = dx - sx + WW / 2;
        if (((unsigned)by < HH) & ((unsigned)bx < WW)) bin = by * WW + bx;

        // 2 channels of this vote's weights (8B, coalesced, L2-hot)
        w = ((const float2*)(feats + (((size_t)(b * LL + s)) * NN + n) * CC))[g];
    }

    float* base = out + (size_t)bl * SLAB + g * QFLOATS;

    // ---- Stream-zero this quantum's 32 KB (8 float4 per thread) ----
    {
        float4* b4 = (float4*)base;
        const float4 z = make_float4(0.f, 0.f, 0.f, 0.f);
#pragma unroll
        for (int i = 0; i < QFLOATS / 4 / 256; i++)
            b4[t + i * 256] = z;
    }

    __syncthreads();   // all zero-stores of this CTA-private quantum complete
                       // & visible before any scattered atomic touches it

    // ---- Scatter: each vote thread commits its 2 channels (REDG, L2-hot) ----
    if (bin >= 0) {
        atomicAdd(base + bin,         w.x);
        atomicAdd(base + PLANE + bin, w.y);
    }
}

extern "C" void kernel_launch(void* const* d_in, const int* in_sizes, int n_in,
                              void* d_out, int out_size)
{
    const float* feats = (const float*)d_in[0];   // [B,L,N,C] f32
    const int*   vsrc  = (const int*)  d_in[1];   // [B,L,2]   i32
    const int*   vdst  = (const int*)  d_in[2];   // [B,L,2]   i32
    const int*   isrc  = (const int*)  d_in[3];   // [B,L,M]   i32
    const int*   idst  = (const int*)  d_in[4];   // [B,L,N]   i32
    float*       out   = (float*)d_out;           // [B,L,C,H,W] f32

    ht_vote_kernel<<<BB * LL * NGRP, 256>>>(feats, vsrc, vdst, isrc, idst, out);
}